// round 15
// baseline (speedup 1.0000x reference)
#include <cuda_runtime.h>
#include <cuda_bf16.h>
#include <math.h>
#include <stdint.h>

// Model dims
#define LAYERS 12
#define DMODEL 768
#define NHEAD  12
#define DK     64
#define FDIM   3072
#define VOCAB  32000
#define BATCH  2
#define SEQ    1024
#define NTOK   (BATCH*SEQ)          // 2048
#define D3     (3*DMODEL)           // 2304
#define K3D    (3*DMODEL)           // 2304 (split-K for K=768)
#define K3F    (3*FDIM)             // 9216 (split-K for K=3072)
#define LN_EPS 1e-5f

// weight-split buffer layout (per layer, element offsets)
#define SZ_QKV  ((long)D3   * K3D)
#define SZ_PROJ ((long)DMODEL * K3D)
#define SZ_FF1  ((long)FDIM * K3D)
#define SZ_FF2  ((long)DMODEL * K3F)
#define OFF_QKV  0L
#define OFF_PROJ (SZ_QKV)
#define OFF_FF1  (SZ_QKV + SZ_PROJ)
#define OFF_FF2  (SZ_QKV + SZ_PROJ + SZ_FF1)
#define PER_LAYER (SZ_QKV + SZ_PROJ + SZ_FF1 + SZ_FF2)

// GEMM smem geometry: K-chunk 32, 4 stages, row stride 40 halves (80B, LDSM conflict-free)
#define KCH    32
#define ASTRD  40
#define A_ST   (128*ASTRD)       // halves per A stage (5120)
#define B_ST   (64*ASTRD)        // halves per B stage (2560)
#define NSTG   4
#define SMEM_BYTES (NSTG*(A_ST + B_ST) * 2)   // 61440 B

// ------------------------- scratch (device globals) -------------------------
__device__ __align__(128) float g_x   [NTOK*DMODEL];
__device__ __align__(128) float g_qkv [NTOK*D3];
__device__ __align__(128) float g_att [BATCH*NHEAD*SEQ*SEQ];
__device__ __align__(128) __nv_bfloat16 g_a3 [ (long)NTOK*K3D ];
__device__ __align__(128) __nv_bfloat16 g_ff3[ (long)NTOK*K3F ];
__device__ __align__(128) __nv_bfloat16 g_w3 [ (long)LAYERS*PER_LAYER ];
__device__ __align__(128) __nv_bfloat16 g_e3 [ (long)VOCAB*K3D ];

// ------------------------- helpers ------------------------------------------
__device__ __forceinline__ void split2(float x, __nv_bfloat16& hi, __nv_bfloat16& lo)
{
    hi = __float2bfloat16(x);
    lo = __float2bfloat16(x - __bfloat162float(hi));
}

#define CP_ASYNC16(dst_u32, src_ptr) \
    asm volatile("cp.async.cg.shared.global [%0], [%1], 16;\n" \
                 :: "r"(dst_u32), "l"(src_ptr))
#define CP_COMMIT()  asm volatile("cp.async.commit_group;\n")
#define CP_WAIT3()   asm volatile("cp.async.wait_group 3;\n")
#define CP_WAIT2()   asm volatile("cp.async.wait_group 2;\n")
#define CP_WAIT1()   asm volatile("cp.async.wait_group 1;\n")
#define CP_WAIT0()   asm volatile("cp.async.wait_group 0;\n")

#define LDSM4(r0,r1,r2,r3, addr) \
    asm volatile("ldmatrix.sync.aligned.m8n8.x4.shared.b16 {%0,%1,%2,%3}, [%4];" \
                 : "=r"(r0),"=r"(r1),"=r"(r2),"=r"(r3) : "r"(addr))

// ------------------------- embed: x = emb[tok] + pos[t] ---------------------
__global__ void embed_k(const int* __restrict__ tokens, const float* __restrict__ emb,
                        const float* __restrict__ pos, float* __restrict__ x)
{
    int row = blockIdx.x;
    int t   = row & (SEQ-1);
    int tok = tokens[row];
    int tid = threadIdx.x;
#pragma unroll
    for (int i = 0; i < 3; i++) {
        int d = tid + i*256;
        x[(long)row*DMODEL + d] = emb[(long)tok*DMODEL + d] + pos[(long)t*DMODEL + d];
    }
}

// ------------------------- layernorm -> split bf16 (A-layout: hi,lo,hi) -----
__global__ void layernorm_k(const float* __restrict__ x, const float* __restrict__ w,
                            const float* __restrict__ bb, __nv_bfloat16* __restrict__ out3)
{
    int row = blockIdx.x;
    const float* xr = x + (long)row*DMODEL;
    int tid = threadIdx.x;
    float v0 = xr[tid], v1 = xr[tid+256], v2 = xr[tid+512];
    float s = v0 + v1 + v2;
    __shared__ float sh[8];
    __shared__ float tot;
#pragma unroll
    for (int o = 16; o; o >>= 1) s += __shfl_xor_sync(0xffffffffu, s, o);
    if ((tid & 31) == 0) sh[tid >> 5] = s;
    __syncthreads();
    if (tid == 0) { float t2 = 0.f; for (int i = 0; i < 8; i++) t2 += sh[i]; tot = t2; }
    __syncthreads();
    float mean = tot * (1.0f/768.0f);
    float d0 = v0-mean, d1 = v1-mean, d2 = v2-mean;
    float sq = d0*d0 + d1*d1 + d2*d2;
    __syncthreads();
#pragma unroll
    for (int o = 16; o; o >>= 1) sq += __shfl_xor_sync(0xffffffffu, sq, o);
    if ((tid & 31) == 0) sh[tid >> 5] = sq;
    __syncthreads();
    if (tid == 0) { float t2 = 0.f; for (int i = 0; i < 8; i++) t2 += sh[i]; tot = t2; }
    __syncthreads();
    float rstd = rsqrtf(tot * (1.0f/768.0f) + LN_EPS);
    long base = (long)row*K3D;
#pragma unroll
    for (int i = 0; i < 3; i++) {
        int k = tid + i*256;
        float dv = (i==0? d0 : i==1? d1 : d2);
        float val = dv*rstd*w[k] + bb[k];
        __nv_bfloat16 hi, lo; split2(val, hi, lo);
        out3[base + k]        = hi;
        out3[base + DMODEL+k] = lo;
        out3[base + 2*DMODEL+k] = hi;
    }
}

// ------------------------- weight transpose + split (B-layout: hi,hi,lo) ----
__global__ void wsplit(const float* __restrict__ W, __nv_bfloat16* __restrict__ out,
                       int K, int N, long wstride, long ostride)
{
    __shared__ float tile[32][33];
    int layer = blockIdx.z;
    const float* Wl = W + (long)layer*wstride;
    __nv_bfloat16* ol = out + (long)layer*ostride;
    int n0 = blockIdx.x*32, k0 = blockIdx.y*32;
    int tx = threadIdx.x, ty = threadIdx.y;
#pragma unroll
    for (int i = 0; i < 32; i += 8)
        tile[ty+i][tx] = Wl[(long)(k0+ty+i)*N + n0 + tx];
    __syncthreads();
#pragma unroll
    for (int i = 0; i < 32; i += 8) {
        int n = n0 + ty + i;
        int k = k0 + tx;
        float x = tile[tx][ty+i];
        __nv_bfloat16 hi, lo; split2(x, hi, lo);
        long base = (long)n*3*K;
        ol[base + k]       = hi;
        ol[base + K + k]   = hi;
        ol[base + 2*K + k] = lo;
    }
}

// ------------------------- emb row split (B-layout, no transpose) -----------
__global__ void esplit(const float* __restrict__ X, __nv_bfloat16* __restrict__ out)
{
    int row = blockIdx.x;
    int tid = threadIdx.x;
    long ib = (long)row*DMODEL;
    long ob = (long)row*K3D;
#pragma unroll
    for (int i = 0; i < 3; i++) {
        int k = tid + i*256;
        float x = X[ib + k];
        __nv_bfloat16 hi, lo; split2(x, hi, lo);
        out[ob + k]          = hi;
        out[ob + DMODEL + k] = hi;
        out[ob + 2*DMODEL+k] = lo;
    }
}

// ------------------------- bf16 split GEMM: C = A3 * B3^T --------------------
// 128x64 tile, K-chunk 32, 4-stage cp.async pipeline, ldmatrix fragments.
// epi: 0=none, 1=+bias, 2=+bias+residual, 3=+bias+GELU -> split bf16 to Dout
__global__ __launch_bounds__(256)
void gemm_bf16(const __nv_bfloat16* __restrict__ A, const __nv_bfloat16* __restrict__ B,
               const float* __restrict__ bias, const float* __restrict__ res,
               float* __restrict__ C, __nv_bfloat16* __restrict__ Dout,
               int M, int N, int K3, int epi)
{
    extern __shared__ __nv_bfloat16 dsm[];
    __nv_bfloat16* AsBase = dsm;                 // [NSTG][A_ST]
    __nv_bfloat16* BsBase = dsm + NSTG*A_ST;     // [NSTG][B_ST]

    int tid  = threadIdx.x;
    int lane = tid & 31;
    int warp = tid >> 5;
    int g = lane >> 2, t = lane & 3;
    int wm = warp >> 1, wn = warp & 1;      // 4 x 2 warp grid, 32x32 warp tile
    long m0 = (long)blockIdx.y * 128;
    long n0 = (long)blockIdx.x * 64;

    uint32_t as_sh = (uint32_t)__cvta_generic_to_shared(AsBase);
    uint32_t bs_sh = (uint32_t)__cvta_generic_to_shared(BsBase);

    float acc[2][4][4];
#pragma unroll
    for (int mt=0;mt<2;mt++)
#pragma unroll
        for (int nt=0;nt<4;nt++)
#pragma unroll
            for (int i=0;i<4;i++) acc[mt][nt][i] = 0.f;

    const int NI = K3 / KCH;

    // stage loader: A 2x16B + B 1x16B per thread
    auto load_stage = [&](int s, int k0) {
#pragma unroll
        for (int j = 0; j < 2; j++) {
            int cid = tid + 256*j;           // 0..511
            int row = cid >> 2, seg = cid & 3;
            uint32_t dst = as_sh + (uint32_t)(s*A_ST + row*ASTRD + seg*8)*2;
            CP_ASYNC16(dst, &A[(m0+row)*K3 + k0 + seg*8]);
        }
        {
            int row = tid >> 2, seg = tid & 3;
            uint32_t dst = bs_sh + (uint32_t)(s*B_ST + row*ASTRD + seg*8)*2;
            CP_ASYNC16(dst, &B[(n0+row)*K3 + k0 + seg*8]);
        }
    };

    load_stage(0, 0);       CP_COMMIT();
    load_stage(1, KCH);     CP_COMMIT();
    load_stage(2, 2*KCH);   CP_COMMIT();

    // ldmatrix lane addressing (precomputed offsets, in halves)
    int a_row = wm*32 + (lane & 15);          // + mt*16
    int a_col = (lane >> 4) * 8;              // + kk*16
    int b_row = wn*32 + ((lane >> 4) << 3) + (lane & 7);   // + np*16
    int b_col = ((lane >> 3) & 1) * 8;        // + kk*16

    for (int i = 0; i < NI; i++) {
        int buf = i & 3;
        if (i + 3 < NI) { load_stage((i+3) & 3, (i+3)*KCH); CP_COMMIT(); CP_WAIT3(); }
        else if (i + 2 < NI) CP_WAIT2();
        else if (i + 1 < NI) CP_WAIT1();
        else                 CP_WAIT0();
        __syncthreads();

        uint32_t abase = as_sh + (uint32_t)(buf*A_ST)*2;
        uint32_t bbase = bs_sh + (uint32_t)(buf*B_ST)*2;
#pragma unroll
        for (int kk = 0; kk < 2; kk++) {
            uint32_t a[2][4], b[2][4];
#pragma unroll
            for (int mt=0; mt<2; mt++) {
                uint32_t ad = abase + (uint32_t)((a_row + mt*16)*ASTRD + a_col + kk*16)*2;
                LDSM4(a[mt][0],a[mt][1],a[mt][2],a[mt][3], ad);
            }
#pragma unroll
            for (int np=0; np<2; np++) {
                uint32_t bd = bbase + (uint32_t)((b_row + np*16)*ASTRD + b_col + kk*16)*2;
                LDSM4(b[np][0],b[np][1],b[np][2],b[np][3], bd);
            }
#pragma unroll
            for (int mt=0;mt<2;mt++)
#pragma unroll
                for (int nt=0;nt<4;nt++) {
                    uint32_t b0 = b[nt>>1][(nt&1)*2], b1 = b[nt>>1][(nt&1)*2+1];
                    asm volatile(
                        "mma.sync.aligned.m16n8k16.row.col.f32.bf16.bf16.f32 "
                        "{%0,%1,%2,%3},{%4,%5,%6,%7},{%8,%9},{%0,%1,%2,%3};"
                        : "+f"(acc[mt][nt][0]), "+f"(acc[mt][nt][1]),
                          "+f"(acc[mt][nt][2]), "+f"(acc[mt][nt][3])
                        : "r"(a[mt][0]),"r"(a[mt][1]),"r"(a[mt][2]),"r"(a[mt][3]),
                          "r"(b0),"r"(b1));
                }
        }
        __syncthreads();
    }

    // epilogue
#pragma unroll
    for (int mt=0;mt<2;mt++) {
#pragma unroll
        for (int half=0; half<2; half++) {
            long r = m0 + wm*32 + mt*16 + g + half*8;
#pragma unroll
            for (int nt=0;nt<4;nt++) {
                long c = n0 + wn*32 + nt*8 + t*2;
                float v0 = acc[mt][nt][half*2+0];
                float v1 = acc[mt][nt][half*2+1];
                if (epi >= 1) { v0 += bias[c]; v1 += bias[c+1]; }
                if (epi == 2) { v0 += res[r*N+c]; v1 += res[r*N+c+1]; }
                if (epi == 3) {
                    v0 = 0.5f*v0*(1.0f + erff(v0*0.70710678118654752f));
                    v1 = 0.5f*v1*(1.0f + erff(v1*0.70710678118654752f));
                    __nv_bfloat16 h0,l0,h1,l1;
                    split2(v0,h0,l0); split2(v1,h1,l1);
                    long base = r*(3L*N);
                    *(__nv_bfloat162*)&Dout[base + c]        = __nv_bfloat162(h0,h1);
                    *(__nv_bfloat162*)&Dout[base + N + c]    = __nv_bfloat162(l0,l1);
                    *(__nv_bfloat162*)&Dout[base + 2L*N + c] = __nv_bfloat162(h0,h1);
                } else {
                    *(float2*)&C[r*N+c] = make_float2(v0, v1);
                }
            }
        }
    }
}

// ------------------------- attention: scores = Q K^T * scale, causal --------
__global__ __launch_bounds__(256)
void attn_scores(const float* __restrict__ qkv, float* __restrict__ att)
{
    int kt = blockIdx.x, qt = blockIdx.y, bh = blockIdx.z;
    if (kt > qt) return;
    int b = bh / NHEAD, h = bh % NHEAD;
    int q0 = qt*64, k0 = kt*64;
    const float* Qb = qkv + (long)b*SEQ*D3 + h*DK;
    const float* Kb = qkv + (long)b*SEQ*D3 + DMODEL + h*DK;
    __shared__ float Qs[64][68];
    __shared__ float Ks[64][68];
    int tid = threadIdx.x;
#pragma unroll
    for (int i = 0; i < 4; i++) {
        int lin = tid*4 + i*1024;
        int r = lin >> 6, c = lin & 63;
        float4 qv = *(const float4*)&Qb[(long)(q0+r)*D3 + c];
        Qs[c+0][r]=qv.x; Qs[c+1][r]=qv.y; Qs[c+2][r]=qv.z; Qs[c+3][r]=qv.w;
        float4 kv = *(const float4*)&Kb[(long)(k0+r)*D3 + c];
        Ks[c+0][r]=kv.x; Ks[c+1][r]=kv.y; Ks[c+2][r]=kv.z; Ks[c+3][r]=kv.w;
    }
    __syncthreads();
    int tx = tid & 15, ty = tid >> 4;
    float acc[4][4];
#pragma unroll
    for (int i=0;i<4;i++)
#pragma unroll
        for (int j=0;j<4;j++) acc[i][j]=0.f;
#pragma unroll 4
    for (int dk = 0; dk < 64; dk++) {
        float4 a = *(float4*)&Qs[dk][ty*4];
        float4 bvec = *(float4*)&Ks[dk][tx*4];
        float aa[4] = {a.x,a.y,a.z,a.w};
        float bb[4] = {bvec.x,bvec.y,bvec.z,bvec.w};
#pragma unroll
        for (int i=0;i<4;i++)
#pragma unroll
            for (int j=0;j<4;j++) acc[i][j] = fmaf(aa[i], bb[j], acc[i][j]);
    }
    const float scl = 0.125f;
#pragma unroll
    for (int i=0;i<4;i++) {
        int r = q0 + ty*4 + i;
#pragma unroll
        for (int j=0;j<4;j++) {
            int c = k0 + tx*4 + j;
            float s = acc[i][j]*scl;
            if (c > r) s = -1e30f;
            att[((long)bh*SEQ + r)*SEQ + c] = s;
        }
    }
}

// ------------------------- softmax per row ----------------------------------
__global__ void attn_softmax(float* __restrict__ att)
{
    int q  = blockIdx.x;
    int bh = blockIdx.y;
    float* row = att + ((long)bh*SEQ + q)*SEQ;
    int nv = q + 1;
    int nw = ((q >> 6) + 1) << 6;
    int tid = threadIdx.x;
    float vals[8];
    float mx = -1e30f;
#pragma unroll
    for (int i = 0; i < 8; i++) {
        int j = tid + i*128;
        vals[i] = (j < nv) ? row[j] : -1e30f;
        mx = fmaxf(mx, vals[i]);
    }
    __shared__ float sh[4];
    __shared__ float tot;
#pragma unroll
    for (int o = 16; o; o >>= 1) mx = fmaxf(mx, __shfl_xor_sync(0xffffffffu, mx, o));
    if ((tid & 31) == 0) sh[tid >> 5] = mx;
    __syncthreads();
    if (tid == 0) tot = fmaxf(fmaxf(sh[0],sh[1]), fmaxf(sh[2],sh[3]));
    __syncthreads();
    mx = tot;
    float s = 0.f;
#pragma unroll
    for (int i = 0; i < 8; i++) {
        int j = tid + i*128;
        vals[i] = (j < nv) ? expf(vals[i] - mx) : 0.f;
        s += vals[i];
    }
    __syncthreads();
#pragma unroll
    for (int o = 16; o; o >>= 1) s += __shfl_xor_sync(0xffffffffu, s, o);
    if ((tid & 31) == 0) sh[tid >> 5] = s;
    __syncthreads();
    if (tid == 0) tot = sh[0]+sh[1]+sh[2]+sh[3];
    __syncthreads();
    float inv = 1.0f / tot;
#pragma unroll
    for (int i = 0; i < 8; i++) {
        int j = tid + i*128;
        if (j < nw) row[j] = vals[i]*inv;
    }
}

// ------------------------- Y = P @ V -> split y3 (A-layout) ------------------
__global__ __launch_bounds__(256)
void attn_pv(const float* __restrict__ att, const float* __restrict__ qkv,
             __nv_bfloat16* __restrict__ y3)
{
    int qt = blockIdx.x, bh = blockIdx.y;
    int b = bh / NHEAD, h = bh % NHEAD;
    int q0 = qt*64;
    const float* Vb = qkv + (long)b*SEQ*D3 + 2*DMODEL + h*DK;
    __shared__ float Ps[64][68];
    __shared__ float Vs[64][68];
    int tid = threadIdx.x;
    int tx = tid & 15, ty = tid >> 4;
    float acc[4][4];
#pragma unroll
    for (int i=0;i<4;i++)
#pragma unroll
        for (int j=0;j<4;j++) acc[i][j]=0.f;

    for (int kt = 0; kt <= qt; kt++) {
        __syncthreads();
#pragma unroll
        for (int i = 0; i < 4; i++) {
            int lin = tid*4 + i*1024;
            int r = lin >> 6, c = lin & 63;
            float4 p = *(const float4*)&att[((long)bh*SEQ + q0 + r)*SEQ + kt*64 + c];
            Ps[c+0][r]=p.x; Ps[c+1][r]=p.y; Ps[c+2][r]=p.z; Ps[c+3][r]=p.w;
            *(float4*)&Vs[r][c] = *(const float4*)&Vb[(long)(kt*64 + r)*D3 + c];
        }
        __syncthreads();
#pragma unroll 4
        for (int k = 0; k < 64; k++) {
            float4 a = *(float4*)&Ps[k][ty*4];
            float4 bvec = *(float4*)&Vs[k][tx*4];
            float aa[4] = {a.x,a.y,a.z,a.w};
            float bb[4] = {bvec.x,bvec.y,bvec.z,bvec.w};
#pragma unroll
            for (int i=0;i<4;i++)
#pragma unroll
                for (int j=0;j<4;j++) acc[i][j] = fmaf(aa[i], bb[j], acc[i][j]);
        }
    }
#pragma unroll
    for (int i=0;i<4;i++) {
        long row = (long)b*SEQ + q0 + ty*4 + i;
        long base = row*K3D;
#pragma unroll
        for (int j=0;j<4;j++) {
            int k = h*DK + tx*4 + j;
            __nv_bfloat16 hi, lo; split2(acc[i][j], hi, lo);
            y3[base + k]            = hi;
            y3[base + DMODEL + k]   = lo;
            y3[base + 2*DMODEL + k] = hi;
        }
    }
}

// ------------------------- host driver --------------------------------------
extern "C" void kernel_launch(void* const* d_in, const int* in_sizes, int n_in,
                              void* d_out, int out_size)
{
    const int*   tokens = (const int*)  d_in[0];
    const float* emb    = (const float*)d_in[1];
    const float* pos    = (const float*)d_in[2];
    const float* ln1_w  = (const float*)d_in[3];
    const float* ln1_b  = (const float*)d_in[4];
    const float* qkv_w  = (const float*)d_in[5];
    const float* qkv_b  = (const float*)d_in[6];
    const float* proj_w = (const float*)d_in[7];
    const float* proj_b = (const float*)d_in[8];
    const float* ln2_w  = (const float*)d_in[9];
    const float* ln2_b  = (const float*)d_in[10];
    const float* ff1_w  = (const float*)d_in[11];
    const float* ff1_b  = (const float*)d_in[12];
    const float* ff2_w  = (const float*)d_in[13];
    const float* ff2_b  = (const float*)d_in[14];
    const float* lnf_w  = (const float*)d_in[15];
    const float* lnf_b  = (const float*)d_in[16];
    float* out = (float*)d_out;

    float *x, *qkv, *att;
    __nv_bfloat16 *a3, *ff3, *w3, *e3;
    cudaGetSymbolAddress((void**)&x,   g_x);
    cudaGetSymbolAddress((void**)&qkv, g_qkv);
    cudaGetSymbolAddress((void**)&att, g_att);
    cudaGetSymbolAddress((void**)&a3,  g_a3);
    cudaGetSymbolAddress((void**)&ff3, g_ff3);
    cudaGetSymbolAddress((void**)&w3,  g_w3);
    cudaGetSymbolAddress((void**)&e3,  g_e3);

    cudaFuncSetAttribute(gemm_bf16, cudaFuncAttributeMaxDynamicSharedMemorySize, SMEM_BYTES);

    embed_k<<<NTOK, 256>>>(tokens, emb, pos, x);
    esplit<<<VOCAB, 256>>>(emb, e3);

    wsplit<<<dim3(D3/32,    DMODEL/32, LAYERS), dim3(32,8)>>>(qkv_w,  w3+OFF_QKV,  DMODEL, D3,    (long)DMODEL*D3,    PER_LAYER);
    wsplit<<<dim3(DMODEL/32,DMODEL/32, LAYERS), dim3(32,8)>>>(proj_w, w3+OFF_PROJ, DMODEL, DMODEL,(long)DMODEL*DMODEL,PER_LAYER);
    wsplit<<<dim3(FDIM/32,  DMODEL/32, LAYERS), dim3(32,8)>>>(ff1_w,  w3+OFF_FF1,  DMODEL, FDIM,  (long)DMODEL*FDIM,  PER_LAYER);
    wsplit<<<dim3(DMODEL/32,FDIM/32,   LAYERS), dim3(32,8)>>>(ff2_w,  w3+OFF_FF2,  FDIM,   DMODEL,(long)FDIM*DMODEL,  PER_LAYER);

    for (int l = 0; l < LAYERS; l++) {
        const __nv_bfloat16* wl = w3 + (long)l*PER_LAYER;
        layernorm_k<<<NTOK, 256>>>(x, ln1_w + l*DMODEL, ln1_b + l*DMODEL, a3);
        gemm_bf16<<<dim3(D3/64, NTOK/128), 256, SMEM_BYTES>>>(a3, wl+OFF_QKV, qkv_b + l*D3,
                                                  nullptr, qkv, nullptr,
                                                  NTOK, D3, K3D, 1);
        attn_scores<<<dim3(SEQ/64, SEQ/64, BATCH*NHEAD), 256>>>(qkv, att);
        attn_softmax<<<dim3(SEQ, BATCH*NHEAD), 128>>>(att);
        attn_pv<<<dim3(SEQ/64, BATCH*NHEAD), 256>>>(att, qkv, a3);
        gemm_bf16<<<dim3(DMODEL/64, NTOK/128), 256, SMEM_BYTES>>>(a3, wl+OFF_PROJ, proj_b + l*DMODEL,
                                                      x, x, nullptr,
                                                      NTOK, DMODEL, K3D, 2);
        layernorm_k<<<NTOK, 256>>>(x, ln2_w + l*DMODEL, ln2_b + l*DMODEL, a3);
        gemm_bf16<<<dim3(FDIM/64, NTOK/128), 256, SMEM_BYTES>>>(a3, wl+OFF_FF1, ff1_b + l*FDIM,
                                                    nullptr, nullptr, ff3,
                                                    NTOK, FDIM, K3D, 3);
        gemm_bf16<<<dim3(DMODEL/64, NTOK/128), 256, SMEM_BYTES>>>(ff3, wl+OFF_FF2, ff2_b + l*DMODEL,
                                                      x, x, nullptr,
                                                      NTOK, DMODEL, K3F, 2);
    }

    layernorm_k<<<NTOK, 256>>>(x, lnf_w, lnf_b, a3);
    gemm_bf16<<<dim3(VOCAB/64, NTOK/128), 256, SMEM_BYTES>>>(a3, e3, nullptr, nullptr, out, nullptr,
                                                 NTOK, VOCAB, K3D, 0);
}

// round 16
// speedup vs baseline: 1.0350x; 1.0350x over previous
#include <cuda_runtime.h>
#include <cuda_bf16.h>
#include <math.h>
#include <stdint.h>

// Model dims
#define LAYERS 12
#define DMODEL 768
#define NHEAD  12
#define DK     64
#define FDIM   3072
#define VOCAB  32000
#define BATCH  2
#define SEQ    1024
#define NTOK   (BATCH*SEQ)          // 2048
#define D3     (3*DMODEL)           // 2304
#define K3D    (3*DMODEL)           // 2304 (split-K for K=768)
#define K3F    (3*FDIM)             // 9216 (split-K for K=3072)
#define LN_EPS 1e-5f

// weight-split buffer layout (per layer, element offsets)
#define SZ_QKV  ((long)D3   * K3D)
#define SZ_PROJ ((long)DMODEL * K3D)
#define SZ_FF1  ((long)FDIM * K3D)
#define SZ_FF2  ((long)DMODEL * K3F)
#define OFF_QKV  0L
#define OFF_PROJ (SZ_QKV)
#define OFF_FF1  (SZ_QKV + SZ_PROJ)
#define OFF_FF2  (SZ_QKV + SZ_PROJ + SZ_FF1)
#define PER_LAYER (SZ_QKV + SZ_PROJ + SZ_FF1 + SZ_FF2)

// GEMM smem geometry: K-chunk 64, row stride 72 halves (144B), 2 stages
#define KCH    64
#define ASTRD  72
#define SMEM_G(BM)  ((2*(BM)*ASTRD + 2*64*ASTRD) * 2)
#define SMEM_128    SMEM_G(128)     // 55296 B
#define SMEM_64     SMEM_G(64)      // 36864 B

// ------------------------- scratch (device globals) -------------------------
__device__ __align__(128) float g_x   [NTOK*DMODEL];
__device__ __align__(128) float g_qkv [NTOK*D3];
__device__ __align__(128) float g_att [BATCH*NHEAD*SEQ*SEQ];
__device__ __align__(128) __nv_bfloat16 g_a3 [ (long)NTOK*K3D ];
__device__ __align__(128) __nv_bfloat16 g_ff3[ (long)NTOK*K3F ];
__device__ __align__(128) __nv_bfloat16 g_w3 [ (long)LAYERS*PER_LAYER ];
__device__ __align__(128) __nv_bfloat16 g_e3 [ (long)VOCAB*K3D ];

// ------------------------- helpers ------------------------------------------
__device__ __forceinline__ void split2(float x, __nv_bfloat16& hi, __nv_bfloat16& lo)
{
    hi = __float2bfloat16(x);
    lo = __float2bfloat16(x - __bfloat162float(hi));
}

#define CP_ASYNC16(dst_u32, src_ptr) \
    asm volatile("cp.async.cg.shared.global [%0], [%1], 16;\n" \
                 :: "r"(dst_u32), "l"(src_ptr))
#define CP_COMMIT()  asm volatile("cp.async.commit_group;\n")
#define CP_WAIT1()   asm volatile("cp.async.wait_group 1;\n")
#define CP_WAIT0()   asm volatile("cp.async.wait_group 0;\n")

// ------------------------- embed: x = emb[tok] + pos[t] ---------------------
__global__ void embed_k(const int* __restrict__ tokens, const float* __restrict__ emb,
                        const float* __restrict__ pos, float* __restrict__ x)
{
    int row = blockIdx.x;
    int t   = row & (SEQ-1);
    int tok = tokens[row];
    int tid = threadIdx.x;
#pragma unroll
    for (int i = 0; i < 3; i++) {
        int d = tid + i*256;
        x[(long)row*DMODEL + d] = emb[(long)tok*DMODEL + d] + pos[(long)t*DMODEL + d];
    }
}

// ------------------------- layernorm -> split bf16 (A-layout: hi,lo,hi) -----
__global__ void layernorm_k(const float* __restrict__ x, const float* __restrict__ w,
                            const float* __restrict__ bb, __nv_bfloat16* __restrict__ out3)
{
    int row = blockIdx.x;
    const float* xr = x + (long)row*DMODEL;
    int tid = threadIdx.x;
    float v0 = xr[tid], v1 = xr[tid+256], v2 = xr[tid+512];
    float s = v0 + v1 + v2;
    __shared__ float sh[8];
    __shared__ float tot;
#pragma unroll
    for (int o = 16; o; o >>= 1) s += __shfl_xor_sync(0xffffffffu, s, o);
    if ((tid & 31) == 0) sh[tid >> 5] = s;
    __syncthreads();
    if (tid == 0) { float t2 = 0.f; for (int i = 0; i < 8; i++) t2 += sh[i]; tot = t2; }
    __syncthreads();
    float mean = tot * (1.0f/768.0f);
    float d0 = v0-mean, d1 = v1-mean, d2 = v2-mean;
    float sq = d0*d0 + d1*d1 + d2*d2;
    __syncthreads();
#pragma unroll
    for (int o = 16; o; o >>= 1) sq += __shfl_xor_sync(0xffffffffu, sq, o);
    if ((tid & 31) == 0) sh[tid >> 5] = sq;
    __syncthreads();
    if (tid == 0) { float t2 = 0.f; for (int i = 0; i < 8; i++) t2 += sh[i]; tot = t2; }
    __syncthreads();
    float rstd = rsqrtf(tot * (1.0f/768.0f) + LN_EPS);
    long base = (long)row*K3D;
#pragma unroll
    for (int i = 0; i < 3; i++) {
        int k = tid + i*256;
        float dv = (i==0? d0 : i==1? d1 : d2);
        float val = dv*rstd*w[k] + bb[k];
        __nv_bfloat16 hi, lo; split2(val, hi, lo);
        out3[base + k]        = hi;
        out3[base + DMODEL+k] = lo;
        out3[base + 2*DMODEL+k] = hi;
    }
}

// ------------------------- weight transpose + split (B-layout: hi,hi,lo) ----
__global__ void wsplit(const float* __restrict__ W, __nv_bfloat16* __restrict__ out,
                       int K, int N, long wstride, long ostride)
{
    __shared__ float tile[32][33];
    int layer = blockIdx.z;
    const float* Wl = W + (long)layer*wstride;
    __nv_bfloat16* ol = out + (long)layer*ostride;
    int n0 = blockIdx.x*32, k0 = blockIdx.y*32;
    int tx = threadIdx.x, ty = threadIdx.y;
#pragma unroll
    for (int i = 0; i < 32; i += 8)
        tile[ty+i][tx] = Wl[(long)(k0+ty+i)*N + n0 + tx];
    __syncthreads();
#pragma unroll
    for (int i = 0; i < 32; i += 8) {
        int n = n0 + ty + i;
        int k = k0 + tx;
        float x = tile[tx][ty+i];
        __nv_bfloat16 hi, lo; split2(x, hi, lo);
        long base = (long)n*3*K;
        ol[base + k]       = hi;
        ol[base + K + k]   = hi;
        ol[base + 2*K + k] = lo;
    }
}

// ------------------------- emb row split (B-layout, no transpose) -----------
__global__ void esplit(const float* __restrict__ X, __nv_bfloat16* __restrict__ out)
{
    int row = blockIdx.x;
    int tid = threadIdx.x;
    long ib = (long)row*DMODEL;
    long ob = (long)row*K3D;
#pragma unroll
    for (int i = 0; i < 3; i++) {
        int k = tid + i*256;
        float x = X[ib + k];
        __nv_bfloat16 hi, lo; split2(x, hi, lo);
        out[ob + k]          = hi;
        out[ob + DMODEL + k] = hi;
        out[ob + 2*DMODEL+k] = lo;
    }
}

// ------------------------- bf16 split GEMM: C = A3 * B3^T --------------------
// Templated CTA tile: BM x 64, K-chunk 64, cp.async 2-stage (R8 mainloop).
// BM=128: warp grid 4x2, 32x32 warp tiles. BM=64: warp grid 2x4, 32x16 tiles.
// epi: 0=none, 1=+bias, 2=+bias+residual, 3=+bias+GELU -> split bf16 to Dout
template<int BM>
__global__ __launch_bounds__(256)
void gemm_bf16(const __nv_bfloat16* __restrict__ A, const __nv_bfloat16* __restrict__ B,
               const float* __restrict__ bias, const float* __restrict__ res,
               float* __restrict__ C, __nv_bfloat16* __restrict__ Dout,
               int M, int N, int K3, int epi)
{
    constexpr int NT  = (BM == 128) ? 4 : 2;   // n-frags per warp
    constexpr int WNW = 8*NT;                  // warp n-width (32 / 16)
    constexpr int A_ST = BM*ASTRD;
    constexpr int B_ST = 64*ASTRD;

    extern __shared__ __nv_bfloat16 dsm[];
    __nv_bfloat16* AsBase = dsm;               // [2][A_ST]
    __nv_bfloat16* BsBase = dsm + 2*A_ST;      // [2][B_ST]

    int tid  = threadIdx.x;
    int lane = tid & 31;
    int warp = tid >> 5;
    int g = lane >> 2, t = lane & 3;
    int wm = (BM == 128) ? (warp >> 1) : (warp >> 2);
    int wn = (BM == 128) ? (warp & 1)  : (warp & 3);
    long m0 = (long)blockIdx.y * BM;
    long n0 = (long)blockIdx.x * 64;

    uint32_t as_sh = (uint32_t)__cvta_generic_to_shared(AsBase);
    uint32_t bs_sh = (uint32_t)__cvta_generic_to_shared(BsBase);

    int lrow = tid >> 3;       // 0..31
    int lseg = tid & 7;        // 0..7 (8 bf16 each)

    float acc[2][NT][4];
#pragma unroll
    for (int mt=0;mt<2;mt++)
#pragma unroll
        for (int nt=0;nt<NT;nt++)
#pragma unroll
            for (int i=0;i<4;i++) acc[mt][nt][i] = 0.f;

    const int NI = K3 / KCH;

    // stage loader: BM/32 A chunks + 2 B chunks per thread (16B each)
    auto load_stage = [&](int s, int k0) {
#pragma unroll
        for (int j = 0; j < BM/32; j++) {
            int row = lrow + j*32;
            uint32_t dst = as_sh + (uint32_t)(s*A_ST + row*ASTRD + lseg*8)*2;
            CP_ASYNC16(dst, &A[(m0+row)*K3 + k0 + lseg*8]);
        }
#pragma unroll
        for (int j = 0; j < 2; j++) {
            int row = lrow + j*32;
            uint32_t dst = bs_sh + (uint32_t)(s*B_ST + row*ASTRD + lseg*8)*2;
            CP_ASYNC16(dst, &B[(n0+row)*K3 + k0 + lseg*8]);
        }
    };

    load_stage(0, 0);
    CP_COMMIT();

    for (int i = 0; i < NI; i++) {
        int buf = i & 1;
        if (i + 1 < NI) {
            load_stage(buf ^ 1, (i+1)*KCH);
            CP_COMMIT();
            CP_WAIT1();
        } else {
            CP_WAIT0();
        }
        __syncthreads();

        const uint32_t* As32 = (const uint32_t*)(AsBase + buf*A_ST);
        const uint32_t* Bs32 = (const uint32_t*)(BsBase + buf*B_ST);
#pragma unroll
        for (int kk = 0; kk < 4; kk++) {
            uint32_t a[2][4], b[NT][2];
#pragma unroll
            for (int mt=0; mt<2; mt++) {
                int r = wm*32 + mt*16 + g;
                a[mt][0] = As32[ r    *(ASTRD/2) + kk*8 + t    ];
                a[mt][1] = As32[(r+8) *(ASTRD/2) + kk*8 + t    ];
                a[mt][2] = As32[ r    *(ASTRD/2) + kk*8 + t + 4];
                a[mt][3] = As32[(r+8) *(ASTRD/2) + kk*8 + t + 4];
            }
#pragma unroll
            for (int nt=0; nt<NT; nt++) {
                int c = wn*WNW + nt*8 + g;
                b[nt][0] = Bs32[c*(ASTRD/2) + kk*8 + t    ];
                b[nt][1] = Bs32[c*(ASTRD/2) + kk*8 + t + 4];
            }
#pragma unroll
            for (int mt=0;mt<2;mt++)
#pragma unroll
                for (int nt=0;nt<NT;nt++)
                    asm volatile(
                        "mma.sync.aligned.m16n8k16.row.col.f32.bf16.bf16.f32 "
                        "{%0,%1,%2,%3},{%4,%5,%6,%7},{%8,%9},{%0,%1,%2,%3};"
                        : "+f"(acc[mt][nt][0]), "+f"(acc[mt][nt][1]),
                          "+f"(acc[mt][nt][2]), "+f"(acc[mt][nt][3])
                        : "r"(a[mt][0]),"r"(a[mt][1]),"r"(a[mt][2]),"r"(a[mt][3]),
                          "r"(b[nt][0]),"r"(b[nt][1]));
        }
        __syncthreads();
    }

    // epilogue
#pragma unroll
    for (int mt=0;mt<2;mt++) {
#pragma unroll
        for (int half=0; half<2; half++) {
            long r = m0 + wm*32 + mt*16 + g + half*8;
#pragma unroll
            for (int nt=0;nt<NT;nt++) {
                long c = n0 + wn*WNW + nt*8 + t*2;
                float v0 = acc[mt][nt][half*2+0];
                float v1 = acc[mt][nt][half*2+1];
                if (epi >= 1) { v0 += bias[c]; v1 += bias[c+1]; }
                if (epi == 2) { v0 += res[r*N+c]; v1 += res[r*N+c+1]; }
                if (epi == 3) {
                    v0 = 0.5f*v0*(1.0f + erff(v0*0.70710678118654752f));
                    v1 = 0.5f*v1*(1.0f + erff(v1*0.70710678118654752f));
                    __nv_bfloat16 h0,l0,h1,l1;
                    split2(v0,h0,l0); split2(v1,h1,l1);
                    long base = r*(3L*N);
                    *(__nv_bfloat162*)&Dout[base + c]        = __nv_bfloat162(h0,h1);
                    *(__nv_bfloat162*)&Dout[base + N + c]    = __nv_bfloat162(l0,l1);
                    *(__nv_bfloat162*)&Dout[base + 2L*N + c] = __nv_bfloat162(h0,h1);
                } else {
                    *(float2*)&C[r*N+c] = make_float2(v0, v1);
                }
            }
        }
    }
}

// ------------------------- attention: scores = Q K^T * scale, causal --------
__global__ __launch_bounds__(256)
void attn_scores(const float* __restrict__ qkv, float* __restrict__ att)
{
    int kt = blockIdx.x, qt = blockIdx.y, bh = blockIdx.z;
    if (kt > qt) return;
    int b = bh / NHEAD, h = bh % NHEAD;
    int q0 = qt*64, k0 = kt*64;
    const float* Qb = qkv + (long)b*SEQ*D3 + h*DK;
    const float* Kb = qkv + (long)b*SEQ*D3 + DMODEL + h*DK;
    __shared__ float Qs[64][68];
    __shared__ float Ks[64][68];
    int tid = threadIdx.x;
#pragma unroll
    for (int i = 0; i < 4; i++) {
        int lin = tid*4 + i*1024;
        int r = lin >> 6, c = lin & 63;
        float4 qv = *(const float4*)&Qb[(long)(q0+r)*D3 + c];
        Qs[c+0][r]=qv.x; Qs[c+1][r]=qv.y; Qs[c+2][r]=qv.z; Qs[c+3][r]=qv.w;
        float4 kv = *(const float4*)&Kb[(long)(k0+r)*D3 + c];
        Ks[c+0][r]=kv.x; Ks[c+1][r]=kv.y; Ks[c+2][r]=kv.z; Ks[c+3][r]=kv.w;
    }
    __syncthreads();
    int tx = tid & 15, ty = tid >> 4;
    float acc[4][4];
#pragma unroll
    for (int i=0;i<4;i++)
#pragma unroll
        for (int j=0;j<4;j++) acc[i][j]=0.f;
#pragma unroll 4
    for (int dk = 0; dk < 64; dk++) {
        float4 a = *(float4*)&Qs[dk][ty*4];
        float4 bvec = *(float4*)&Ks[dk][tx*4];
        float aa[4] = {a.x,a.y,a.z,a.w};
        float bb[4] = {bvec.x,bvec.y,bvec.z,bvec.w};
#pragma unroll
        for (int i=0;i<4;i++)
#pragma unroll
            for (int j=0;j<4;j++) acc[i][j] = fmaf(aa[i], bb[j], acc[i][j]);
    }
    const float scl = 0.125f;
#pragma unroll
    for (int i=0;i<4;i++) {
        int r = q0 + ty*4 + i;
#pragma unroll
        for (int j=0;j<4;j++) {
            int c = k0 + tx*4 + j;
            float s = acc[i][j]*scl;
            if (c > r) s = -1e30f;
            att[((long)bh*SEQ + r)*SEQ + c] = s;
        }
    }
}

// ------------------------- softmax per row ----------------------------------
__global__ void attn_softmax(float* __restrict__ att)
{
    int q  = blockIdx.x;
    int bh = blockIdx.y;
    float* row = att + ((long)bh*SEQ + q)*SEQ;
    int nv = q + 1;
    int nw = ((q >> 6) + 1) << 6;
    int tid = threadIdx.x;
    float vals[8];
    float mx = -1e30f;
#pragma unroll
    for (int i = 0; i < 8; i++) {
        int j = tid + i*128;
        vals[i] = (j < nv) ? row[j] : -1e30f;
        mx = fmaxf(mx, vals[i]);
    }
    __shared__ float sh[4];
    __shared__ float tot;
#pragma unroll
    for (int o = 16; o; o >>= 1) mx = fmaxf(mx, __shfl_xor_sync(0xffffffffu, mx, o));
    if ((tid & 31) == 0) sh[tid >> 5] = mx;
    __syncthreads();
    if (tid == 0) tot = fmaxf(fmaxf(sh[0],sh[1]), fmaxf(sh[2],sh[3]));
    __syncthreads();
    mx = tot;
    float s = 0.f;
#pragma unroll
    for (int i = 0; i < 8; i++) {
        int j = tid + i*128;
        vals[i] = (j < nv) ? expf(vals[i] - mx) : 0.f;
        s += vals[i];
    }
    __syncthreads();
#pragma unroll
    for (int o = 16; o; o >>= 1) s += __shfl_xor_sync(0xffffffffu, s, o);
    if ((tid & 31) == 0) sh[tid >> 5] = s;
    __syncthreads();
    if (tid == 0) tot = sh[0]+sh[1]+sh[2]+sh[3];
    __syncthreads();
    float inv = 1.0f / tot;
#pragma unroll
    for (int i = 0; i < 8; i++) {
        int j = tid + i*128;
        if (j < nw) row[j] = vals[i]*inv;
    }
}

// ------------------------- Y = P @ V -> split y3 (A-layout) ------------------
__global__ __launch_bounds__(256)
void attn_pv(const float* __restrict__ att, const float* __restrict__ qkv,
             __nv_bfloat16* __restrict__ y3)
{
    int qt = blockIdx.x, bh = blockIdx.y;
    int b = bh / NHEAD, h = bh % NHEAD;
    int q0 = qt*64;
    const float* Vb = qkv + (long)b*SEQ*D3 + 2*DMODEL + h*DK;
    __shared__ float Ps[64][68];
    __shared__ float Vs[64][68];
    int tid = threadIdx.x;
    int tx = tid & 15, ty = tid >> 4;
    float acc[4][4];
#pragma unroll
    for (int i=0;i<4;i++)
#pragma unroll
        for (int j=0;j<4;j++) acc[i][j]=0.f;

    for (int kt = 0; kt <= qt; kt++) {
        __syncthreads();
#pragma unroll
        for (int i = 0; i < 4; i++) {
            int lin = tid*4 + i*1024;
            int r = lin >> 6, c = lin & 63;
            float4 p = *(const float4*)&att[((long)bh*SEQ + q0 + r)*SEQ + kt*64 + c];
            Ps[c+0][r]=p.x; Ps[c+1][r]=p.y; Ps[c+2][r]=p.z; Ps[c+3][r]=p.w;
            *(float4*)&Vs[r][c] = *(const float4*)&Vb[(long)(kt*64 + r)*D3 + c];
        }
        __syncthreads();
#pragma unroll 4
        for (int k = 0; k < 64; k++) {
            float4 a = *(float4*)&Ps[k][ty*4];
            float4 bvec = *(float4*)&Vs[k][tx*4];
            float aa[4] = {a.x,a.y,a.z,a.w};
            float bb[4] = {bvec.x,bvec.y,bvec.z,bvec.w};
#pragma unroll
            for (int i=0;i<4;i++)
#pragma unroll
                for (int j=0;j<4;j++) acc[i][j] = fmaf(aa[i], bb[j], acc[i][j]);
        }
    }
#pragma unroll
    for (int i=0;i<4;i++) {
        long row = (long)b*SEQ + q0 + ty*4 + i;
        long base = row*K3D;
#pragma unroll
        for (int j=0;j<4;j++) {
            int k = h*DK + tx*4 + j;
            __nv_bfloat16 hi, lo; split2(acc[i][j], hi, lo);
            y3[base + k]            = hi;
            y3[base + DMODEL + k]   = lo;
            y3[base + 2*DMODEL + k] = hi;
        }
    }
}

// ------------------------- host driver --------------------------------------
extern "C" void kernel_launch(void* const* d_in, const int* in_sizes, int n_in,
                              void* d_out, int out_size)
{
    const int*   tokens = (const int*)  d_in[0];
    const float* emb    = (const float*)d_in[1];
    const float* pos    = (const float*)d_in[2];
    const float* ln1_w  = (const float*)d_in[3];
    const float* ln1_b  = (const float*)d_in[4];
    const float* qkv_w  = (const float*)d_in[5];
    const float* qkv_b  = (const float*)d_in[6];
    const float* proj_w = (const float*)d_in[7];
    const float* proj_b = (const float*)d_in[8];
    const float* ln2_w  = (const float*)d_in[9];
    const float* ln2_b  = (const float*)d_in[10];
    const float* ff1_w  = (const float*)d_in[11];
    const float* ff1_b  = (const float*)d_in[12];
    const float* ff2_w  = (const float*)d_in[13];
    const float* ff2_b  = (const float*)d_in[14];
    const float* lnf_w  = (const float*)d_in[15];
    const float* lnf_b  = (const float*)d_in[16];
    float* out = (float*)d_out;

    float *x, *qkv, *att;
    __nv_bfloat16 *a3, *ff3, *w3, *e3;
    cudaGetSymbolAddress((void**)&x,   g_x);
    cudaGetSymbolAddress((void**)&qkv, g_qkv);
    cudaGetSymbolAddress((void**)&att, g_att);
    cudaGetSymbolAddress((void**)&a3,  g_a3);
    cudaGetSymbolAddress((void**)&ff3, g_ff3);
    cudaGetSymbolAddress((void**)&w3,  g_w3);
    cudaGetSymbolAddress((void**)&e3,  g_e3);

    cudaFuncSetAttribute(gemm_bf16<128>, cudaFuncAttributeMaxDynamicSharedMemorySize, SMEM_128);
    cudaFuncSetAttribute(gemm_bf16<64>,  cudaFuncAttributeMaxDynamicSharedMemorySize, SMEM_64);

    embed_k<<<NTOK, 256>>>(tokens, emb, pos, x);
    esplit<<<VOCAB, 256>>>(emb, e3);

    wsplit<<<dim3(D3/32,    DMODEL/32, LAYERS), dim3(32,8)>>>(qkv_w,  w3+OFF_QKV,  DMODEL, D3,    (long)DMODEL*D3,    PER_LAYER);
    wsplit<<<dim3(DMODEL/32,DMODEL/32, LAYERS), dim3(32,8)>>>(proj_w, w3+OFF_PROJ, DMODEL, DMODEL,(long)DMODEL*DMODEL,PER_LAYER);
    wsplit<<<dim3(FDIM/32,  DMODEL/32, LAYERS), dim3(32,8)>>>(ff1_w,  w3+OFF_FF1,  DMODEL, FDIM,  (long)DMODEL*FDIM,  PER_LAYER);
    wsplit<<<dim3(DMODEL/32,FDIM/32,   LAYERS), dim3(32,8)>>>(ff2_w,  w3+OFF_FF2,  FDIM,   DMODEL,(long)FDIM*DMODEL,  PER_LAYER);

    for (int l = 0; l < LAYERS; l++) {
        const __nv_bfloat16* wl = w3 + (long)l*PER_LAYER;
        layernorm_k<<<NTOK, 256>>>(x, ln1_w + l*DMODEL, ln1_b + l*DMODEL, a3);
        gemm_bf16<128><<<dim3(D3/64, NTOK/128), 256, SMEM_128>>>(a3, wl+OFF_QKV, qkv_b + l*D3,
                                                  nullptr, qkv, nullptr,
                                                  NTOK, D3, K3D, 1);
        attn_scores<<<dim3(SEQ/64, SEQ/64, BATCH*NHEAD), 256>>>(qkv, att);
        attn_softmax<<<dim3(SEQ, BATCH*NHEAD), 128>>>(att);
        attn_pv<<<dim3(SEQ/64, BATCH*NHEAD), 256>>>(att, qkv, a3);
        gemm_bf16<64><<<dim3(DMODEL/64, NTOK/64), 256, SMEM_64>>>(a3, wl+OFF_PROJ, proj_b + l*DMODEL,
                                                      x, x, nullptr,
                                                      NTOK, DMODEL, K3D, 2);
        layernorm_k<<<NTOK, 256>>>(x, ln2_w + l*DMODEL, ln2_b + l*DMODEL, a3);
        gemm_bf16<128><<<dim3(FDIM/64, NTOK/128), 256, SMEM_128>>>(a3, wl+OFF_FF1, ff1_b + l*FDIM,
                                                    nullptr, nullptr, ff3,
                                                    NTOK, FDIM, K3D, 3);
        gemm_bf16<64><<<dim3(DMODEL/64, NTOK/64), 256, SMEM_64>>>(ff3, wl+OFF_FF2, ff2_b + l*DMODEL,
                                                      x, x, nullptr,
                                                      NTOK, DMODEL, K3F, 2);
    }

    layernorm_k<<<NTOK, 256>>>(x, lnf_w, lnf_b, a3);
    gemm_bf16<128><<<dim3(VOCAB/64, NTOK/128), 256, SMEM_128>>>(a3, e3, nullptr, nullptr, out, nullptr,
                                                 NTOK, VOCAB, K3D, 0);
}

// round 17
// speedup vs baseline: 1.0889x; 1.0522x over previous
#include <cuda_runtime.h>
#include <cuda_bf16.h>
#include <math.h>
#include <stdint.h>

// Model dims
#define LAYERS 12
#define DMODEL 768
#define NHEAD  12
#define DK     64
#define FDIM   3072
#define VOCAB  32000
#define BATCH  2
#define SEQ    1024
#define NTOK   (BATCH*SEQ)          // 2048
#define D3     (3*DMODEL)           // 2304
#define K3D    (3*DMODEL)           // 2304 (split-K for K=768)
#define K3F    (3*FDIM)             // 9216 (split-K for K=3072)
#define LN_EPS 1e-5f

// weight-split buffer layout (per layer, element offsets)
#define SZ_QKV  ((long)D3   * K3D)
#define SZ_PROJ ((long)DMODEL * K3D)
#define SZ_FF1  ((long)FDIM * K3D)
#define SZ_FF2  ((long)DMODEL * K3F)
#define OFF_QKV  0L
#define OFF_PROJ (SZ_QKV)
#define OFF_FF1  (SZ_QKV + SZ_PROJ)
#define OFF_FF2  (SZ_QKV + SZ_PROJ + SZ_FF1)
#define PER_LAYER (SZ_QKV + SZ_PROJ + SZ_FF1 + SZ_FF2)

// GEMM smem geometry: K-chunk 128, row stride 136 halves (272B), 2 stages,
// single __syncthreads per chunk.
#define KCH    128
#define ASTRD  136
#define SMEM_G(BM)  ((2*(BM)*ASTRD + 2*64*ASTRD) * 2)
#define SMEM_128    SMEM_G(128)     // 104448 B -> 2 CTA/SM
#define SMEM_64     SMEM_G(64)      // 69632 B  -> 3 CTA/SM

// ------------------------- scratch (device globals) -------------------------
__device__ __align__(128) float g_x   [NTOK*DMODEL];
__device__ __align__(128) float g_qkv [NTOK*D3];
__device__ __align__(128) float g_att [BATCH*NHEAD*SEQ*SEQ];
__device__ __align__(128) __nv_bfloat16 g_a3 [ (long)NTOK*K3D ];
__device__ __align__(128) __nv_bfloat16 g_ff3[ (long)NTOK*K3F ];
__device__ __align__(128) __nv_bfloat16 g_w3 [ (long)LAYERS*PER_LAYER ];
__device__ __align__(128) __nv_bfloat16 g_e3 [ (long)VOCAB*K3D ];

// ------------------------- helpers ------------------------------------------
__device__ __forceinline__ void split2(float x, __nv_bfloat16& hi, __nv_bfloat16& lo)
{
    hi = __float2bfloat16(x);
    lo = __float2bfloat16(x - __bfloat162float(hi));
}

#define CP_ASYNC16(dst_u32, src_ptr) \
    asm volatile("cp.async.cg.shared.global [%0], [%1], 16;\n" \
                 :: "r"(dst_u32), "l"(src_ptr))
#define CP_COMMIT()  asm volatile("cp.async.commit_group;\n")
#define CP_WAIT0()   asm volatile("cp.async.wait_group 0;\n")

// ------------------------- embed: x = emb[tok] + pos[t] ---------------------
__global__ void embed_k(const int* __restrict__ tokens, const float* __restrict__ emb,
                        const float* __restrict__ pos, float* __restrict__ x)
{
    int row = blockIdx.x;
    int t   = row & (SEQ-1);
    int tok = tokens[row];
    int tid = threadIdx.x;
#pragma unroll
    for (int i = 0; i < 3; i++) {
        int d = tid + i*256;
        x[(long)row*DMODEL + d] = emb[(long)tok*DMODEL + d] + pos[(long)t*DMODEL + d];
    }
}

// ------------------------- layernorm -> split bf16 (A-layout: hi,lo,hi) -----
__global__ void layernorm_k(const float* __restrict__ x, const float* __restrict__ w,
                            const float* __restrict__ bb, __nv_bfloat16* __restrict__ out3)
{
    int row = blockIdx.x;
    const float* xr = x + (long)row*DMODEL;
    int tid = threadIdx.x;
    float v0 = xr[tid], v1 = xr[tid+256], v2 = xr[tid+512];
    float s = v0 + v1 + v2;
    __shared__ float sh[8];
    __shared__ float tot;
#pragma unroll
    for (int o = 16; o; o >>= 1) s += __shfl_xor_sync(0xffffffffu, s, o);
    if ((tid & 31) == 0) sh[tid >> 5] = s;
    __syncthreads();
    if (tid == 0) { float t2 = 0.f; for (int i = 0; i < 8; i++) t2 += sh[i]; tot = t2; }
    __syncthreads();
    float mean = tot * (1.0f/768.0f);
    float d0 = v0-mean, d1 = v1-mean, d2 = v2-mean;
    float sq = d0*d0 + d1*d1 + d2*d2;
    __syncthreads();
#pragma unroll
    for (int o = 16; o; o >>= 1) sq += __shfl_xor_sync(0xffffffffu, sq, o);
    if ((tid & 31) == 0) sh[tid >> 5] = sq;
    __syncthreads();
    if (tid == 0) { float t2 = 0.f; for (int i = 0; i < 8; i++) t2 += sh[i]; tot = t2; }
    __syncthreads();
    float rstd = rsqrtf(tot * (1.0f/768.0f) + LN_EPS);
    long base = (long)row*K3D;
#pragma unroll
    for (int i = 0; i < 3; i++) {
        int k = tid + i*256;
        float dv = (i==0? d0 : i==1? d1 : d2);
        float val = dv*rstd*w[k] + bb[k];
        __nv_bfloat16 hi, lo; split2(val, hi, lo);
        out3[base + k]        = hi;
        out3[base + DMODEL+k] = lo;
        out3[base + 2*DMODEL+k] = hi;
    }
}

// ------------------------- weight transpose + split (B-layout: hi,hi,lo) ----
__global__ void wsplit(const float* __restrict__ W, __nv_bfloat16* __restrict__ out,
                       int K, int N, long wstride, long ostride)
{
    __shared__ float tile[32][33];
    int layer = blockIdx.z;
    const float* Wl = W + (long)layer*wstride;
    __nv_bfloat16* ol = out + (long)layer*ostride;
    int n0 = blockIdx.x*32, k0 = blockIdx.y*32;
    int tx = threadIdx.x, ty = threadIdx.y;
#pragma unroll
    for (int i = 0; i < 32; i += 8)
        tile[ty+i][tx] = Wl[(long)(k0+ty+i)*N + n0 + tx];
    __syncthreads();
#pragma unroll
    for (int i = 0; i < 32; i += 8) {
        int n = n0 + ty + i;
        int k = k0 + tx;
        float x = tile[tx][ty+i];
        __nv_bfloat16 hi, lo; split2(x, hi, lo);
        long base = (long)n*3*K;
        ol[base + k]       = hi;
        ol[base + K + k]   = hi;
        ol[base + 2*K + k] = lo;
    }
}

// ------------------------- emb row split (B-layout, no transpose) -----------
__global__ void esplit(const float* __restrict__ X, __nv_bfloat16* __restrict__ out)
{
    int row = blockIdx.x;
    int tid = threadIdx.x;
    long ib = (long)row*DMODEL;
    long ob = (long)row*K3D;
#pragma unroll
    for (int i = 0; i < 3; i++) {
        int k = tid + i*256;
        float x = X[ib + k];
        __nv_bfloat16 hi, lo; split2(x, hi, lo);
        out[ob + k]          = hi;
        out[ob + DMODEL + k] = hi;
        out[ob + 2*DMODEL+k] = lo;
    }
}

// ------------------------- bf16 split GEMM: C = A3 * B3^T --------------------
// Templated CTA tile: BM x 64, K-chunk 128, cp.async 2-stage, ONE sync/chunk.
// BM=128: warp grid 4x2, 32x32 warp tiles. BM=64: warp grid 2x4, 32x16 tiles.
// epi: 0=none, 1=+bias, 2=+bias+residual, 3=+bias+GELU -> split bf16 to Dout
template<int BM>
__global__ __launch_bounds__(256)
void gemm_bf16(const __nv_bfloat16* __restrict__ A, const __nv_bfloat16* __restrict__ B,
               const float* __restrict__ bias, const float* __restrict__ res,
               float* __restrict__ C, __nv_bfloat16* __restrict__ Dout,
               int M, int N, int K3, int epi)
{
    constexpr int NT  = (BM == 128) ? 4 : 2;   // n-frags per warp
    constexpr int WNW = 8*NT;                  // warp n-width (32 / 16)
    constexpr int A_ST = BM*ASTRD;
    constexpr int B_ST = 64*ASTRD;

    extern __shared__ __nv_bfloat16 dsm[];
    __nv_bfloat16* AsBase = dsm;               // [2][A_ST]
    __nv_bfloat16* BsBase = dsm + 2*A_ST;      // [2][B_ST]

    int tid  = threadIdx.x;
    int lane = tid & 31;
    int warp = tid >> 5;
    int g = lane >> 2, t = lane & 3;
    int wm = (BM == 128) ? (warp >> 1) : (warp >> 2);
    int wn = (BM == 128) ? (warp & 1)  : (warp & 3);
    long m0 = (long)blockIdx.y * BM;
    long n0 = (long)blockIdx.x * 64;

    uint32_t as_sh = (uint32_t)__cvta_generic_to_shared(AsBase);
    uint32_t bs_sh = (uint32_t)__cvta_generic_to_shared(BsBase);

    float acc[2][NT][4];
#pragma unroll
    for (int mt=0;mt<2;mt++)
#pragma unroll
        for (int nt=0;nt<NT;nt++)
#pragma unroll
            for (int i=0;i<4;i++) acc[mt][nt][i] = 0.f;

    const int NI = K3 / KCH;

    // stage loader: rows of 128 halves = 16 x 16B segments
    auto load_stage = [&](int s, int k0) {
#pragma unroll
        for (int j = 0; j < BM/16; j++) {
            int cid = tid + 256*j;
            int row = cid >> 4, seg = cid & 15;
            uint32_t dst = as_sh + (uint32_t)(s*A_ST + row*ASTRD + seg*8)*2;
            CP_ASYNC16(dst, &A[(m0+row)*K3 + k0 + seg*8]);
        }
#pragma unroll
        for (int j = 0; j < 4; j++) {
            int cid = tid + 256*j;
            int row = cid >> 4, seg = cid & 15;
            uint32_t dst = bs_sh + (uint32_t)(s*B_ST + row*ASTRD + seg*8)*2;
            CP_ASYNC16(dst, &B[(n0+row)*K3 + k0 + seg*8]);
        }
    };

    load_stage(0, 0);
    CP_COMMIT();

    for (int i = 0; i < NI; i++) {
        int buf = i & 1;
        CP_WAIT0();              // buf's data (committed last iter) complete
        __syncthreads();         // publish to all warps; orders prev reads before next loads
        if (i + 1 < NI) {
            load_stage(buf ^ 1, (i+1)*KCH);   // overlaps with compute below
            CP_COMMIT();
        }

        const uint32_t* As32 = (const uint32_t*)(AsBase + buf*A_ST);
        const uint32_t* Bs32 = (const uint32_t*)(BsBase + buf*B_ST);
#pragma unroll
        for (int kk = 0; kk < 8; kk++) {
            uint32_t a[2][4], b[NT][2];
#pragma unroll
            for (int mt=0; mt<2; mt++) {
                int r = wm*32 + mt*16 + g;
                a[mt][0] = As32[ r    *(ASTRD/2) + kk*8 + t    ];
                a[mt][1] = As32[(r+8) *(ASTRD/2) + kk*8 + t    ];
                a[mt][2] = As32[ r    *(ASTRD/2) + kk*8 + t + 4];
                a[mt][3] = As32[(r+8) *(ASTRD/2) + kk*8 + t + 4];
            }
#pragma unroll
            for (int nt=0; nt<NT; nt++) {
                int c = wn*WNW + nt*8 + g;
                b[nt][0] = Bs32[c*(ASTRD/2) + kk*8 + t    ];
                b[nt][1] = Bs32[c*(ASTRD/2) + kk*8 + t + 4];
            }
#pragma unroll
            for (int mt=0;mt<2;mt++)
#pragma unroll
                for (int nt=0;nt<NT;nt++)
                    asm volatile(
                        "mma.sync.aligned.m16n8k16.row.col.f32.bf16.bf16.f32 "
                        "{%0,%1,%2,%3},{%4,%5,%6,%7},{%8,%9},{%0,%1,%2,%3};"
                        : "+f"(acc[mt][nt][0]), "+f"(acc[mt][nt][1]),
                          "+f"(acc[mt][nt][2]), "+f"(acc[mt][nt][3])
                        : "r"(a[mt][0]),"r"(a[mt][1]),"r"(a[mt][2]),"r"(a[mt][3]),
                          "r"(b[nt][0]),"r"(b[nt][1]));
        }
    }

    // epilogue (no smem use -> no trailing sync needed)
#pragma unroll
    for (int mt=0;mt<2;mt++) {
#pragma unroll
        for (int half=0; half<2; half++) {
            long r = m0 + wm*32 + mt*16 + g + half*8;
#pragma unroll
            for (int nt=0;nt<NT;nt++) {
                long c = n0 + wn*WNW + nt*8 + t*2;
                float v0 = acc[mt][nt][half*2+0];
                float v1 = acc[mt][nt][half*2+1];
                if (epi >= 1) { v0 += bias[c]; v1 += bias[c+1]; }
                if (epi == 2) { v0 += res[r*N+c]; v1 += res[r*N+c+1]; }
                if (epi == 3) {
                    v0 = 0.5f*v0*(1.0f + erff(v0*0.70710678118654752f));
                    v1 = 0.5f*v1*(1.0f + erff(v1*0.70710678118654752f));
                    __nv_bfloat16 h0,l0,h1,l1;
                    split2(v0,h0,l0); split2(v1,h1,l1);
                    long base = r*(3L*N);
                    *(__nv_bfloat162*)&Dout[base + c]        = __nv_bfloat162(h0,h1);
                    *(__nv_bfloat162*)&Dout[base + N + c]    = __nv_bfloat162(l0,l1);
                    *(__nv_bfloat162*)&Dout[base + 2L*N + c] = __nv_bfloat162(h0,h1);
                } else {
                    *(float2*)&C[r*N+c] = make_float2(v0, v1);
                }
            }
        }
    }
}

// ------------------------- attention: scores = Q K^T * scale, causal --------
__global__ __launch_bounds__(256)
void attn_scores(const float* __restrict__ qkv, float* __restrict__ att)
{
    int kt = blockIdx.x, qt = blockIdx.y, bh = blockIdx.z;
    if (kt > qt) return;
    int b = bh / NHEAD, h = bh % NHEAD;
    int q0 = qt*64, k0 = kt*64;
    const float* Qb = qkv + (long)b*SEQ*D3 + h*DK;
    const float* Kb = qkv + (long)b*SEQ*D3 + DMODEL + h*DK;
    __shared__ float Qs[64][68];
    __shared__ float Ks[64][68];
    int tid = threadIdx.x;
#pragma unroll
    for (int i = 0; i < 4; i++) {
        int lin = tid*4 + i*1024;
        int r = lin >> 6, c = lin & 63;
        float4 qv = *(const float4*)&Qb[(long)(q0+r)*D3 + c];
        Qs[c+0][r]=qv.x; Qs[c+1][r]=qv.y; Qs[c+2][r]=qv.z; Qs[c+3][r]=qv.w;
        float4 kv = *(const float4*)&Kb[(long)(k0+r)*D3 + c];
        Ks[c+0][r]=kv.x; Ks[c+1][r]=kv.y; Ks[c+2][r]=kv.z; Ks[c+3][r]=kv.w;
    }
    __syncthreads();
    int tx = tid & 15, ty = tid >> 4;
    float acc[4][4];
#pragma unroll
    for (int i=0;i<4;i++)
#pragma unroll
        for (int j=0;j<4;j++) acc[i][j]=0.f;
#pragma unroll 4
    for (int dk = 0; dk < 64; dk++) {
        float4 a = *(float4*)&Qs[dk][ty*4];
        float4 bvec = *(float4*)&Ks[dk][tx*4];
        float aa[4] = {a.x,a.y,a.z,a.w};
        float bb[4] = {bvec.x,bvec.y,bvec.z,bvec.w};
#pragma unroll
        for (int i=0;i<4;i++)
#pragma unroll
            for (int j=0;j<4;j++) acc[i][j] = fmaf(aa[i], bb[j], acc[i][j]);
    }
    const float scl = 0.125f;
#pragma unroll
    for (int i=0;i<4;i++) {
        int r = q0 + ty*4 + i;
#pragma unroll
        for (int j=0;j<4;j++) {
            int c = k0 + tx*4 + j;
            float s = acc[i][j]*scl;
            if (c > r) s = -1e30f;
            att[((long)bh*SEQ + r)*SEQ + c] = s;
        }
    }
}

// ------------------------- softmax per row ----------------------------------
__global__ void attn_softmax(float* __restrict__ att)
{
    int q  = blockIdx.x;
    int bh = blockIdx.y;
    float* row = att + ((long)bh*SEQ + q)*SEQ;
    int nv = q + 1;
    int nw = ((q >> 6) + 1) << 6;
    int tid = threadIdx.x;
    float vals[8];
    float mx = -1e30f;
#pragma unroll
    for (int i = 0; i < 8; i++) {
        int j = tid + i*128;
        vals[i] = (j < nv) ? row[j] : -1e30f;
        mx = fmaxf(mx, vals[i]);
    }
    __shared__ float sh[4];
    __shared__ float tot;
#pragma unroll
    for (int o = 16; o; o >>= 1) mx = fmaxf(mx, __shfl_xor_sync(0xffffffffu, mx, o));
    if ((tid & 31) == 0) sh[tid >> 5] = mx;
    __syncthreads();
    if (tid == 0) tot = fmaxf(fmaxf(sh[0],sh[1]), fmaxf(sh[2],sh[3]));
    __syncthreads();
    mx = tot;
    float s = 0.f;
#pragma unroll
    for (int i = 0; i < 8; i++) {
        int j = tid + i*128;
        vals[i] = (j < nv) ? expf(vals[i] - mx) : 0.f;
        s += vals[i];
    }
    __syncthreads();
#pragma unroll
    for (int o = 16; o; o >>= 1) s += __shfl_xor_sync(0xffffffffu, s, o);
    if ((tid & 31) == 0) sh[tid >> 5] = s;
    __syncthreads();
    if (tid == 0) tot = sh[0]+sh[1]+sh[2]+sh[3];
    __syncthreads();
    float inv = 1.0f / tot;
#pragma unroll
    for (int i = 0; i < 8; i++) {
        int j = tid + i*128;
        if (j < nw) row[j] = vals[i]*inv;
    }
}

// ------------------------- Y = P @ V -> split y3 (A-layout) ------------------
__global__ __launch_bounds__(256)
void attn_pv(const float* __restrict__ att, const float* __restrict__ qkv,
             __nv_bfloat16* __restrict__ y3)
{
    int qt = blockIdx.x, bh = blockIdx.y;
    int b = bh / NHEAD, h = bh % NHEAD;
    int q0 = qt*64;
    const float* Vb = qkv + (long)b*SEQ*D3 + 2*DMODEL + h*DK;
    __shared__ float Ps[64][68];
    __shared__ float Vs[64][68];
    int tid = threadIdx.x;
    int tx = tid & 15, ty = tid >> 4;
    float acc[4][4];
#pragma unroll
    for (int i=0;i<4;i++)
#pragma unroll
        for (int j=0;j<4;j++) acc[i][j]=0.f;

    for (int kt = 0; kt <= qt; kt++) {
        __syncthreads();
#pragma unroll
        for (int i = 0; i < 4; i++) {
            int lin = tid*4 + i*1024;
            int r = lin >> 6, c = lin & 63;
            float4 p = *(const float4*)&att[((long)bh*SEQ + q0 + r)*SEQ + kt*64 + c];
            Ps[c+0][r]=p.x; Ps[c+1][r]=p.y; Ps[c+2][r]=p.z; Ps[c+3][r]=p.w;
            *(float4*)&Vs[r][c] = *(const float4*)&Vb[(long)(kt*64 + r)*D3 + c];
        }
        __syncthreads();
#pragma unroll 4
        for (int k = 0; k < 64; k++) {
            float4 a = *(float4*)&Ps[k][ty*4];
            float4 bvec = *(float4*)&Vs[k][tx*4];
            float aa[4] = {a.x,a.y,a.z,a.w};
            float bb[4] = {bvec.x,bvec.y,bvec.z,bvec.w};
#pragma unroll
            for (int i=0;i<4;i++)
#pragma unroll
                for (int j=0;j<4;j++) acc[i][j] = fmaf(aa[i], bb[j], acc[i][j]);
        }
    }
#pragma unroll
    for (int i=0;i<4;i++) {
        long row = (long)b*SEQ + q0 + ty*4 + i;
        long base = row*K3D;
#pragma unroll
        for (int j=0;j<4;j++) {
            int k = h*DK + tx*4 + j;
            __nv_bfloat16 hi, lo; split2(acc[i][j], hi, lo);
            y3[base + k]            = hi;
            y3[base + DMODEL + k]   = lo;
            y3[base + 2*DMODEL + k] = hi;
        }
    }
}

// ------------------------- host driver --------------------------------------
extern "C" void kernel_launch(void* const* d_in, const int* in_sizes, int n_in,
                              void* d_out, int out_size)
{
    const int*   tokens = (const int*)  d_in[0];
    const float* emb    = (const float*)d_in[1];
    const float* pos    = (const float*)d_in[2];
    const float* ln1_w  = (const float*)d_in[3];
    const float* ln1_b  = (const float*)d_in[4];
    const float* qkv_w  = (const float*)d_in[5];
    const float* qkv_b  = (const float*)d_in[6];
    const float* proj_w = (const float*)d_in[7];
    const float* proj_b = (const float*)d_in[8];
    const float* ln2_w  = (const float*)d_in[9];
    const float* ln2_b  = (const float*)d_in[10];
    const float* ff1_w  = (const float*)d_in[11];
    const float* ff1_b  = (const float*)d_in[12];
    const float* ff2_w  = (const float*)d_in[13];
    const float* ff2_b  = (const float*)d_in[14];
    const float* lnf_w  = (const float*)d_in[15];
    const float* lnf_b  = (const float*)d_in[16];
    float* out = (float*)d_out;

    float *x, *qkv, *att;
    __nv_bfloat16 *a3, *ff3, *w3, *e3;
    cudaGetSymbolAddress((void**)&x,   g_x);
    cudaGetSymbolAddress((void**)&qkv, g_qkv);
    cudaGetSymbolAddress((void**)&att, g_att);
    cudaGetSymbolAddress((void**)&a3,  g_a3);
    cudaGetSymbolAddress((void**)&ff3, g_ff3);
    cudaGetSymbolAddress((void**)&w3,  g_w3);
    cudaGetSymbolAddress((void**)&e3,  g_e3);

    cudaFuncSetAttribute(gemm_bf16<128>, cudaFuncAttributeMaxDynamicSharedMemorySize, SMEM_128);
    cudaFuncSetAttribute(gemm_bf16<64>,  cudaFuncAttributeMaxDynamicSharedMemorySize, SMEM_64);

    embed_k<<<NTOK, 256>>>(tokens, emb, pos, x);
    esplit<<<VOCAB, 256>>>(emb, e3);

    wsplit<<<dim3(D3/32,    DMODEL/32, LAYERS), dim3(32,8)>>>(qkv_w,  w3+OFF_QKV,  DMODEL, D3,    (long)DMODEL*D3,    PER_LAYER);
    wsplit<<<dim3(DMODEL/32,DMODEL/32, LAYERS), dim3(32,8)>>>(proj_w, w3+OFF_PROJ, DMODEL, DMODEL,(long)DMODEL*DMODEL,PER_LAYER);
    wsplit<<<dim3(FDIM/32,  DMODEL/32, LAYERS), dim3(32,8)>>>(ff1_w,  w3+OFF_FF1,  DMODEL, FDIM,  (long)DMODEL*FDIM,  PER_LAYER);
    wsplit<<<dim3(DMODEL/32,FDIM/32,   LAYERS), dim3(32,8)>>>(ff2_w,  w3+OFF_FF2,  FDIM,   DMODEL,(long)FDIM*DMODEL,  PER_LAYER);

    for (int l = 0; l < LAYERS; l++) {
        const __nv_bfloat16* wl = w3 + (long)l*PER_LAYER;
        layernorm_k<<<NTOK, 256>>>(x, ln1_w + l*DMODEL, ln1_b + l*DMODEL, a3);
        gemm_bf16<128><<<dim3(D3/64, NTOK/128), 256, SMEM_128>>>(a3, wl+OFF_QKV, qkv_b + l*D3,
                                                  nullptr, qkv, nullptr,
                                                  NTOK, D3, K3D, 1);
        attn_scores<<<dim3(SEQ/64, SEQ/64, BATCH*NHEAD), 256>>>(qkv, att);
        attn_softmax<<<dim3(SEQ, BATCH*NHEAD), 128>>>(att);
        attn_pv<<<dim3(SEQ/64, BATCH*NHEAD), 256>>>(att, qkv, a3);
        gemm_bf16<64><<<dim3(DMODEL/64, NTOK/64), 256, SMEM_64>>>(a3, wl+OFF_PROJ, proj_b + l*DMODEL,
                                                      x, x, nullptr,
                                                      NTOK, DMODEL, K3D, 2);
        layernorm_k<<<NTOK, 256>>>(x, ln2_w + l*DMODEL, ln2_b + l*DMODEL, a3);
        gemm_bf16<128><<<dim3(FDIM/64, NTOK/128), 256, SMEM_128>>>(a3, wl+OFF_FF1, ff1_b + l*FDIM,
                                                    nullptr, nullptr, ff3,
                                                    NTOK, FDIM, K3D, 3);
        gemm_bf16<64><<<dim3(DMODEL/64, NTOK/64), 256, SMEM_64>>>(ff3, wl+OFF_FF2, ff2_b + l*DMODEL,
                                                      x, x, nullptr,
                                                      NTOK, DMODEL, K3F, 2);
    }

    layernorm_k<<<NTOK, 256>>>(x, lnf_w, lnf_b, a3);
    gemm_bf16<128><<<dim3(VOCAB/64, NTOK/128), 256, SMEM_128>>>(a3, e3, nullptr, nullptr, out, nullptr,
                                                 NTOK, VOCAB, K3D, 0);
}